// round 7
// baseline (speedup 1.0000x reference)
#include <cuda_runtime.h>
#include <cuda_fp16.h>
#include <cstdint>

#define N_TOK    65536
#define KCODES   8192
#define ZQ_ELEMS 4194304
#define NT       256
#define NCH      64          // 4096 codes per half / 64 per chunk
#define ACC_TH   1.5f        // rescore window, acc domain (= 3.66e-4 in dd domain)
#define FLT_BIG  3.402823e38f

// ---- smem layout (bytes) ----
#define SOFF_Z   0           // 32768 : z tile [d64][m128] fp32 (kept live for rescore)
#define SOFF_B   32768       // 16896 : B frags [buf2][(nt4+ks)*33 + L] uint2 (padded)
#define SOFF_EN  49664       // 2*64*4
#define SOFF_ZN  50176       // 128*4
#define SMEM_SZ  50688
#define BSTRIDE  2112        // uint32 units per buffer

__device__ float              g_enorm[KCODES];
__device__ unsigned long long g_best[N_TOK];
__device__ float              g_loss;

__device__ __forceinline__ uint32_t pack2h(float lo, float hi){
    uint32_t r; asm("cvt.rn.f16x2.f32 %0, %1, %2;" : "=r"(r) : "f"(hi), "f"(lo)); return r;
}
// fp16 mma with fp16 accumulator (2 packed regs) — 2x-rate hypothesis
__device__ __forceinline__ void mma_fp16h(uint32_t* d, const uint32_t* a, uint32_t b0, uint32_t b1){
    asm volatile("mma.sync.aligned.m16n8k16.row.col.f16.f16.f16.f16 "
        "{%0,%1}, {%2,%3,%4,%5}, {%6,%7}, {%0,%1};"
        : "+r"(d[0]), "+r"(d[1])
        : "r"(a[0]), "r"(a[1]), "r"(a[2]), "r"(a[3]), "r"(b0), "r"(b1));
}
__device__ __forceinline__ unsigned long long packbi(float dd, int idx){
    uint32_t u = __float_as_uint(dd);
    u = (u & 0x80000000u) ? ~u : (u | 0x80000000u);
    return ((unsigned long long)u << 32) | (uint32_t)idx;
}

// ---------------------------------------------------------------------------
// K1: ||e_k||^2 (sequential fmaf, d ascending), init g_best, zero loss
// ---------------------------------------------------------------------------
__global__ void vq_pre(const float* __restrict__ emb){
    int t = blockIdx.x * 256 + threadIdx.x;
    if (t < KCODES){
        const float4* r = (const float4*)(emb + t*64);
        float s = 0.f;
        #pragma unroll
        for (int i = 0; i < 16; i++){
            float4 v = __ldg(&r[i]);
            s = fmaf(v.x,v.x,s); s = fmaf(v.y,v.y,s); s = fmaf(v.z,v.z,s); s = fmaf(v.w,v.w,s);
        }
        g_enorm[t] = s;
    }
    if (t < N_TOK) g_best[t] = 0xFFFFFFFFFFFFFFFFull;
    if (t == 0) g_loss = 0.f;
}

// ---------------------------------------------------------------------------
// K2: fp16 mma / fp16 acc, top-5 per lane + exact fp32 rescore + atomicMin.
// grid (512 token tiles, 2 code halves); CTA = 128 tokens x 4096 codes.
// ---------------------------------------------------------------------------
__global__ __launch_bounds__(NT, 2) void vq_main(const float* __restrict__ z,
                                                 const float* __restrict__ emb){
    extern __shared__ __align__(16) char smem[];
    float*    zS  = (float*)(smem + SOFF_Z);
    uint32_t* Bs  = (uint32_t*)(smem + SOFF_B);
    float*    enS = (float*)(smem + SOFF_EN);
    float*    znS = (float*)(smem + SOFF_ZN);

    int tid = threadIdx.x, wid = tid >> 5, lane = tid & 31;
    int n0 = blockIdx.x * 128;
    int kbase = blockIdx.y * 4096;
    const float* zb = z + (n0 >> 12) * 262144 + (n0 & 4095);

    for (int i = tid; i < 64*128; i += NT){
        int d = i >> 7, m = i & 127;
        zS[d*128 + m] = zb[d*4096 + m];
    }
    __syncthreads();

    if (tid < 128){
        float s = 0.f;
        #pragma unroll
        for (int d = 0; d < 64; d++){ float v = zS[d*128 + tid]; s = fmaf(v, v, s); }
        znS[tid] = s;
    }

    // A fragments in registers (loop-invariant)
    uint32_t Af[4][4];
    {
        int r0 = wid*16 + (lane >> 2);
        #pragma unroll
        for (int ks = 0; ks < 4; ks++){
            int k0 = ks*16 + (lane & 3)*2;
            Af[ks][0] = pack2h(zS[(k0  )*128 + r0  ], zS[(k0+1)*128 + r0  ]);
            Af[ks][1] = pack2h(zS[(k0  )*128 + r0+8], zS[(k0+1)*128 + r0+8]);
            Af[ks][2] = pack2h(zS[(k0+8)*128 + r0  ], zS[(k0+9)*128 + r0  ]);
            Af[ks][3] = pack2h(zS[(k0+8)*128 + r0+8], zS[(k0+9)*128 + r0+8]);
        }
    }

    // produce chunk 0 into buffer 0
    {
        const float4* src = (const float4*)(emb + (size_t)(kbase)*64);
        #pragma unroll
        for (int j = 0; j < 4; j++){
            int f = j*256 + tid;
            float4 v = __ldg(&src[f]);
            int n = f >> 4, k0 = (f & 15)*4;
            uint32_t u0 = pack2h(v.x*8192.f, v.y*8192.f);
            uint32_t u1 = pack2h(v.z*8192.f, v.w*8192.f);
            int nt = n >> 3, ks = k0 >> 4, p = (k0 >> 3) & 1;
            int Lt = (n & 7)*4 + ((k0 & 7) >> 1);
            uint32_t* dst = Bs + ((nt*4 + ks)*33 + Lt)*2 + p;
            dst[0] = u0; dst[2] = u1;
        }
        if (tid < 64) enS[tid] = __ldg(&g_enorm[kbase + tid]);
    }
    __syncthreads();

    // top-5 per lane, 2 rows (acc domain: larger = better)
    float s0[5], s1[5]; int ix0[5], ix1[5];
    #pragma unroll
    for (int j = 0; j < 5; j++){ s0[j] = -FLT_BIG; s1[j] = -FLT_BIG; ix0[j] = 0; ix1[j] = 0; }

    auto ins5 = [](float (&s)[5], int (&ix)[5], float v, int kk){
        if (v > s[4]){
            if (v > s[0]){ s[4]=s[3];ix[4]=ix[3]; s[3]=s[2];ix[3]=ix[2]; s[2]=s[1];ix[2]=ix[1]; s[1]=s[0];ix[1]=ix[0]; s[0]=v;ix[0]=kk; }
            else if (v > s[1]){ s[4]=s[3];ix[4]=ix[3]; s[3]=s[2];ix[3]=ix[2]; s[2]=s[1];ix[2]=ix[1]; s[1]=v;ix[1]=kk; }
            else if (v > s[2]){ s[4]=s[3];ix[4]=ix[3]; s[3]=s[2];ix[3]=ix[2]; s[2]=v;ix[2]=kk; }
            else if (v > s[3]){ s[4]=s[3];ix[4]=ix[3]; s[3]=v;ix[3]=kk; }
            else { s[4]=v; ix[4]=kk; }
        }
    };

    #pragma unroll 1
    for (int c = 0; c < NCH; c++){
        int buf = c & 1;
        float4 pv[4];
        bool more = (c + 1 < NCH);
        if (more){
            const float4* src = (const float4*)(emb + (size_t)(kbase + (c+1)*64)*64);
            #pragma unroll
            for (int j = 0; j < 4; j++) pv[j] = __ldg(&src[j*256 + tid]);
        }

        // acc init: f16x2(-4096*en0, -4096*en1), same for both row-regs
        uint32_t acc[8][2];
        #pragma unroll
        for (int nt = 0; nt < 8; nt++){
            int c0 = nt*8 + (lane & 3)*2;
            float2 en2 = *(const float2*)&enS[buf*64 + c0];
            uint32_t iv = pack2h(en2.x * -4096.f, en2.y * -4096.f);
            acc[nt][0] = iv; acc[nt][1] = iv;
        }

        const uint32_t* Bb = Bs + buf*BSTRIDE;
        #pragma unroll
        for (int ks = 0; ks < 4; ks++){
            #pragma unroll
            for (int nt = 0; nt < 8; nt++){
                uint2 b = *(const uint2*)(Bb + ((nt*4 + ks)*33 + lane)*2);
                mma_fp16h(acc[nt], Af[ks], b.x, b.y);
            }
        }

        // epilogue: unpack + guarded top-5 insert
        int kk0 = kbase + c*64;
        #pragma unroll
        for (int nt = 0; nt < 8; nt++){
            int c0 = nt*8 + (lane & 3)*2;
            int kA = kk0 + c0, kB = kA + 1;
            float2 v0 = __half22float2(*(const __half2*)&acc[nt][0]);  // row r0:  (kA, kB)
            float2 v1 = __half22float2(*(const __half2*)&acc[nt][1]);  // row r0+8
            if (fmaxf(v0.x, v0.y) > s0[4]){ ins5(s0, ix0, v0.x, kA); ins5(s0, ix0, v0.y, kB); }
            if (fmaxf(v1.x, v1.y) > s1[4]){ ins5(s1, ix1, v1.x, kA); ins5(s1, ix1, v1.y, kB); }
        }

        if (more){
            uint32_t* BW = Bs + (buf^1)*BSTRIDE;
            #pragma unroll
            for (int j = 0; j < 4; j++){
                int f = j*256 + tid;
                int n = f >> 4, k0 = (f & 15)*4;
                uint32_t u0 = pack2h(pv[j].x*8192.f, pv[j].y*8192.f);
                uint32_t u1 = pack2h(pv[j].z*8192.f, pv[j].w*8192.f);
                int nt = n >> 3, ks = k0 >> 4, p = (k0 >> 3) & 1;
                int Lt = (n & 7)*4 + ((k0 & 7) >> 1);
                uint32_t* dst = BW + ((nt*4 + ks)*33 + Lt)*2 + p;
                dst[0] = u0; dst[2] = u1;
            }
            if (tid < 64) enS[(buf^1)*64 + tid] = __ldg(&g_enorm[kbase + (c+1)*64 + tid]);
        }
        __syncthreads();
    }

    // quad max then exact fp32 rescore of all within-window candidates
    float q0 = s0[0], q1 = s1[0];
    #pragma unroll
    for (int off = 1; off <= 2; off <<= 1){
        q0 = fmaxf(q0, __shfl_xor_sync(0xFFFFFFFF, q0, off));
        q1 = fmaxf(q1, __shfl_xor_sync(0xFFFFFFFF, q1, off));
    }
    float thr0 = q0 - ACC_TH, thr1 = q1 - ACC_TH;
    int r0 = wid*16 + (lane >> 2);
    float zn0 = znS[r0], zn1 = znS[r0 + 8];

    auto rescore = [&](int rloc, float sv, int idx, float thr, float zn){
        if (sv >= thr){
            const float4* ep = (const float4*)(emb + idx*64);
            float dot = 0.f;
            #pragma unroll 4
            for (int q = 0; q < 16; q++){
                float4 ev = __ldg(&ep[q]);
                int d = q*4;
                dot = fmaf(zS[(d  )*128 + rloc], ev.x, dot);
                dot = fmaf(zS[(d+1)*128 + rloc], ev.y, dot);
                dot = fmaf(zS[(d+2)*128 + rloc], ev.z, dot);
                dot = fmaf(zS[(d+3)*128 + rloc], ev.w, dot);
            }
            float dd = fmaf(-2.f, dot, zn + __ldg(&g_enorm[idx]));   // exact (R2-validated) formula
            atomicMin(&g_best[n0 + rloc], packbi(dd, idx));
        }
    };
    #pragma unroll
    for (int j = 0; j < 5; j++){
        rescore(r0,     s0[j], ix0[j], thr0, zn0);
        rescore(r0 + 8, s1[j], ix1[j], thr1, zn1);
    }
}

// ---------------------------------------------------------------------------
// K3: gather z_q, straight-through output, loss partial, index output
// ---------------------------------------------------------------------------
__global__ void vq_out(const float* __restrict__ z, const float* __restrict__ emb,
                       float* __restrict__ outz, float* __restrict__ outIdxF, int writeF){
    int tid = threadIdx.x;
    int n0 = blockIdx.x * 64;
    const int b = n0 >> 12; const int hw0 = n0 & 4095;
    const float* zb = z    + b*262144 + hw0;
    float*       ob = outz + b*262144 + hw0;

    __shared__ int idxs[64];
    if (tid < 64){
        int idx = (int)(g_best[n0 + tid] & 0xFFFFFFFFull);
        idxs[tid] = idx;
        if (writeF) outIdxF[n0 + tid] = (float)idx;
    }
    __syncthreads();

    float ls = 0.f;
    for (int i = tid; i < 64*64; i += 256){
        int c = i >> 6, m = i & 63;
        float e  = __ldg(&emb[idxs[m]*64 + c]);
        float zv = zb[c*4096 + m];
        float t  = e - zv;
        ob[c*4096 + m] = zv + t;      // fl(zc + fl(zq - zc)) — STE rounding replicated
        ls = fmaf(t, t, ls);
    }
    __shared__ float red[256];
    red[tid] = ls; __syncthreads();
    for (int s = 128; s > 0; s >>= 1){
        if (tid < s) red[tid] += red[tid + s];
        __syncthreads();
    }
    if (tid == 0) atomicAdd(&g_loss, red[0]);
}

__global__ void vq_fin(float* __restrict__ out, int full){
    if (full){
        float m = g_loss * (1.f / (float)ZQ_ELEMS);
        out[ZQ_ELEMS] = m + 0.25f * m;
    }
}

// ---------------------------------------------------------------------------
extern "C" void kernel_launch(void* const* d_in, const int* in_sizes, int n_in,
                              void* d_out, int out_size){
    const float* z   = (const float*)d_in[0];
    const float* emb = (const float*)d_in[1];
    float* out = (float*)d_out;

    int full = (out_size >= ZQ_ELEMS + 1 + N_TOK) ? 1 : 0;

    cudaFuncSetAttribute(vq_main, cudaFuncAttributeMaxDynamicSharedMemorySize, SMEM_SZ);

    vq_pre<<<N_TOK/256, 256>>>(emb);
    dim3 grid(N_TOK/128, 2);
    vq_main<<<grid, NT, SMEM_SZ>>>(z, emb);
    vq_out<<<N_TOK/64, 256>>>(z, emb, out, full ? (out + ZQ_ELEMS + 1) : out, full);
    vq_fin<<<1, 1>>>(out, full);
}